// round 2
// baseline (speedup 1.0000x reference)
#include <cuda_runtime.h>

#define SL 1024
#define NE 4
#define ND 128
#define NBATCH 4
#define KA (SL*NE)

typedef unsigned long long u64;

// ---- scratch (no allocs allowed) ----
__device__ float g_pi[(size_t)NBATCH*KA*ND];
__device__ float g_po[(size_t)NBATCH*KA*ND];
__device__ float g_ni[(size_t)NBATCH*SL*ND];
__device__ float g_no[(size_t)NBATCH*SL*ND];
__device__ float g_st[(size_t)NBATCH*SL*ND];

// ---- packed f32x2 helpers ----
__device__ __forceinline__ u64 pk2(float a, float b){
    u64 r; asm("mov.b64 %0,{%1,%2};":"=l"(r):"r"(__float_as_uint(a)),"r"(__float_as_uint(b))); return r;
}
__device__ __forceinline__ void upk2(u64 v, float&a, float&b){
    unsigned lo,hi; asm("mov.b64 {%0,%1},%2;":"=r"(lo),"=r"(hi):"l"(v));
    a=__uint_as_float(lo); b=__uint_as_float(hi);
}
__device__ __forceinline__ void fma2(u64&d, u64 a, u64 b){
    asm("fma.rn.f32x2 %0,%1,%2,%0;":"+l"(d):"l"(a),"l"(b));
}
__device__ __forceinline__ float sigm(float v){ return 1.f/(1.f+__expf(-v)); }

struct Smem {
    u64   A2[16][64];     // A tile, each value duplicated as f32x2
    float Bs[16][128];    // B tile
};
struct GSmem { Smem g; float ro[64][ND]; };   // exactly 48 KB

// ---- shared 64x128 GEMM core: acc += A[64xK] @ B[Kx128] ----
// SEG3: A streamed from three 64x128 sources (8 K-tiles each), else flat with lda.
template<int NT, bool SEG3>
__device__ __forceinline__ void gemm64(
    const float* a0, const float* a1, const float* a2, int lda,
    const float* __restrict__ Bmat, u64 (&acc)[4][4], Smem& sm)
{
    const int tid = threadIdx.x;
    const int r0 = (tid>>4)*4;          // 4 rows
    const int c0 = (tid&15)*8;          // 8 cols
    const int arow = tid>>2, ac=(tid&3)*4;
    const int bw = tid>>5, bc=(tid&31)*4;

    float4 ra, rb0, rb1;
    ra  = *(const float4*)(a0 + (size_t)arow*lda + ac);
    rb0 = *(const float4*)(Bmat + bw*ND + bc);
    rb1 = *(const float4*)(Bmat + (bw+8)*ND + bc);

#pragma unroll 1
    for (int kt=0; kt<NT; ++kt){
        sm.A2[ac+0][arow]=pk2(ra.x,ra.x);
        sm.A2[ac+1][arow]=pk2(ra.y,ra.y);
        sm.A2[ac+2][arow]=pk2(ra.z,ra.z);
        sm.A2[ac+3][arow]=pk2(ra.w,ra.w);
        *(float4*)&sm.Bs[bw][bc]   = rb0;
        *(float4*)&sm.Bs[bw+8][bc] = rb1;
        __syncthreads();
        if (kt+1<NT){
            const int kn=kt+1;
            const float* ap; int off;
            if (SEG3){ ap=(kn<8)?a0:((kn<16)?a1:a2); off=(kn&7)*16; }
            else     { ap=a0; off=kn*16; }
            ra = *(const float4*)(ap + (size_t)arow*lda + off + ac);
            const float* bp = Bmat + (size_t)kn*16*ND;
            rb0 = *(const float4*)(bp + bw*ND + bc);
            rb1 = *(const float4*)(bp + (bw+8)*ND + bc);
        }
#pragma unroll
        for (int kk=0;kk<16;++kk){
            u64 a0v=sm.A2[kk][r0], a1v=sm.A2[kk][r0+1], a2v=sm.A2[kk][r0+2], a3v=sm.A2[kk][r0+3];
            ulonglong2 b01 = *(const ulonglong2*)&sm.Bs[kk][c0];
            ulonglong2 b23 = *(const ulonglong2*)&sm.Bs[kk][c0+4];
            fma2(acc[0][0],a0v,b01.x); fma2(acc[0][1],a0v,b01.y); fma2(acc[0][2],a0v,b23.x); fma2(acc[0][3],a0v,b23.y);
            fma2(acc[1][0],a1v,b01.x); fma2(acc[1][1],a1v,b01.y); fma2(acc[1][2],a1v,b23.x); fma2(acc[1][3],a1v,b23.y);
            fma2(acc[2][0],a2v,b01.x); fma2(acc[2][1],a2v,b01.y); fma2(acc[2][2],a2v,b23.x); fma2(acc[2][3],a2v,b23.y);
            fma2(acc[3][0],a3v,b01.x); fma2(acc[3][1],a3v,b01.y); fma2(acc[3][2],a3v,b23.x); fma2(acc[3][3],a3v,b23.y);
        }
        __syncthreads();
    }
}

#define ZERO_ACC(acc) { _Pragma("unroll") for(int i=0;i<4;++i){ _Pragma("unroll") for(int j=0;j<4;++j) acc[i][j]=0ull; } }

// ---- kernel 1: per-edge projections  pi/po[b, s*E+e, :] = state[b,s,:] @ W[e] + bias[e]
__global__ void __launch_bounds__(256) proj_kernel(
    const float* __restrict__ x,
    const float* __restrict__ W_ein, const float* __restrict__ b_ein,
    const float* __restrict__ W_eout, const float* __restrict__ b_eout, int use_x)
{
    __shared__ Smem sm;
    const int stile=blockIdx.x, e=blockIdx.y>>1, dir=blockIdx.y&1, b=blockIdx.z;
    const float* src = (use_x? x : (const float*)g_st) + (size_t)b*SL*ND + (size_t)stile*64*ND;
    const float* W   = (dir? W_eout : W_ein) + (size_t)e*ND*ND;
    const float* bias= (dir? b_eout : b_ein) + e*ND;
    float* dst = (dir? g_po : g_pi) + (size_t)b*KA*ND;

    u64 acc[4][4]; ZERO_ACC(acc);
    gemm64<8,false>(src, src, src, ND, W, acc, sm);

    const int tid=threadIdx.x, r0=(tid>>4)*4, c0=(tid&15)*8;
#pragma unroll
    for (int i=0;i<4;++i){
        const int s = stile*64 + r0 + i;
        float* drow = dst + ((size_t)s*NE + e)*ND;
        float v0,v1,v2,v3;
        upk2(acc[i][0],v0,v1); upk2(acc[i][1],v2,v3);
        *(float4*)(drow+c0)   = make_float4(v0+bias[c0],v1+bias[c0+1],v2+bias[c0+2],v3+bias[c0+3]);
        upk2(acc[i][2],v0,v1); upk2(acc[i][3],v2,v3);
        *(float4*)(drow+c0+4) = make_float4(v0+bias[c0+4],v1+bias[c0+5],v2+bias[c0+6],v3+bias[c0+7]);
    }
}

// ---- kernel 2: aggregation  node[b,s,:] = A[b,s,:] @ P[b]   (K=4096)
__global__ void __launch_bounds__(256) agg_kernel(
    const float* __restrict__ A_in, const float* __restrict__ A_out)
{
    __shared__ Smem sm;
    const int stile=blockIdx.x, dir=blockIdx.y, b=blockIdx.z;
    const float* A = (dir? A_out : A_in) + (size_t)b*SL*KA + (size_t)stile*64*KA;
    const float* P = (dir? g_po : g_pi) + (size_t)b*KA*ND;
    float* dst = (dir? g_no : g_ni) + (size_t)b*SL*ND + (size_t)stile*64*ND;

    u64 acc[4][4]; ZERO_ACC(acc);
    gemm64<256,false>(A, A, A, KA, P, acc, sm);

    const int tid=threadIdx.x, r0=(tid>>4)*4, c0=(tid&15)*8;
#pragma unroll
    for (int i=0;i<4;++i){
        float* drow = dst + (size_t)(r0+i)*ND;
        float v0,v1,v2,v3;
        upk2(acc[i][0],v0,v1); upk2(acc[i][1],v2,v3);
        *(float4*)(drow+c0)   = make_float4(v0,v1,v2,v3);
        upk2(acc[i][2],v0,v1); upk2(acc[i][3],v2,v3);
        *(float4*)(drow+c0+4) = make_float4(v0,v1,v2,v3);
    }
}

// ---- kernel 3: fused GRU update over 64 rows ----
__global__ void __launch_bounds__(256) gru_kernel(
    const float* __restrict__ x,
    const float* __restrict__ W_r, const float* __restrict__ b_r,
    const float* __restrict__ W_z, const float* __restrict__ b_z,
    const float* __restrict__ W_h, const float* __restrict__ b_h,
    float* __restrict__ dout, int use_x, int is_final)
{
    __shared__ GSmem s;
    const int stile=blockIdx.x, b=blockIdx.z;
    const size_t base=(size_t)b*SL*ND + (size_t)stile*64*ND;
    const float* ni=g_ni+base; const float* no=g_no+base;
    const float* st=(use_x? x : (const float*)g_st)+base;
    const int tid=threadIdx.x, r0=(tid>>4)*4, c0=(tid&15)*8;

    u64 acc[4][4];
    // r gate
    ZERO_ACC(acc);
    gemm64<24,true>(ni,no,st,ND,W_r,acc,s.g);

    float stv[4][8];
#pragma unroll
    for (int i=0;i<4;++i){
        float4 p0=*(const float4*)(st+(size_t)(r0+i)*ND+c0);
        float4 p1=*(const float4*)(st+(size_t)(r0+i)*ND+c0+4);
        stv[i][0]=p0.x; stv[i][1]=p0.y; stv[i][2]=p0.z; stv[i][3]=p0.w;
        stv[i][4]=p1.x; stv[i][5]=p1.y; stv[i][6]=p1.z; stv[i][7]=p1.w;
    }
    // ro = sigmoid(r)*state -> smem
#pragma unroll
    for (int i=0;i<4;++i)
#pragma unroll
        for (int j=0;j<4;++j){
            float v0,v1; upk2(acc[i][j],v0,v1);
            const int c=c0+2*j;
            s.ro[r0+i][c]   = sigm(v0+b_r[c])  *stv[i][2*j];
            s.ro[r0+i][c+1] = sigm(v1+b_r[c+1])*stv[i][2*j+1];
        }
    __syncthreads();

    // z gate
    ZERO_ACC(acc);
    gemm64<24,true>(ni,no,st,ND,W_z,acc,s.g);
    float zv[4][8];
#pragma unroll
    for (int i=0;i<4;++i)
#pragma unroll
        for (int j=0;j<4;++j){
            float v0,v1; upk2(acc[i][j],v0,v1);
            zv[i][2*j]  =sigm(v0+b_z[c0+2*j]);
            zv[i][2*j+1]=sigm(v1+b_z[c0+2*j+1]);
        }

    // h_hat
    ZERO_ACC(acc);
    gemm64<24,true>(ni,no,(const float*)s.ro,ND,W_h,acc,s.g);

    float* ost = g_st + base;
    float* od  = dout + base;
#pragma unroll
    for (int i=0;i<4;++i){
        float o[8];
#pragma unroll
        for (int j=0;j<4;++j){
            float v0,v1; upk2(acc[i][j],v0,v1);
            float h0=tanhf(v0+b_h[c0+2*j]), h1=tanhf(v1+b_h[c0+2*j+1]);
            o[2*j]  =(1.f-zv[i][2*j])  *stv[i][2*j]  + zv[i][2*j]  *h0;
            o[2*j+1]=(1.f-zv[i][2*j+1])*stv[i][2*j+1] + zv[i][2*j+1]*h1;
        }
        *(float4*)(ost+(size_t)(r0+i)*ND+c0)   = make_float4(o[0],o[1],o[2],o[3]);
        *(float4*)(ost+(size_t)(r0+i)*ND+c0+4) = make_float4(o[4],o[5],o[6],o[7]);
        if (is_final){
            *(float4*)(od+(size_t)(r0+i)*ND+c0)   = make_float4(o[0],o[1],o[2],o[3]);
            *(float4*)(od+(size_t)(r0+i)*ND+c0+4) = make_float4(o[4],o[5],o[6],o[7]);
        }
    }
}

extern "C" void kernel_launch(void* const* d_in, const int* in_sizes, int n_in,
                              void* d_out, int out_size)
{
    const float* x      = (const float*)d_in[0];
    const float* A_in   = (const float*)d_in[1];
    const float* A_out  = (const float*)d_in[2];
    const float* W_ein  = (const float*)d_in[3];
    const float* b_ein  = (const float*)d_in[4];
    const float* W_eout = (const float*)d_in[5];
    const float* b_eout = (const float*)d_in[6];
    const float* W_r    = (const float*)d_in[7];
    const float* b_r    = (const float*)d_in[8];
    const float* W_z    = (const float*)d_in[9];
    const float* b_z    = (const float*)d_in[10];
    const float* W_h    = (const float*)d_in[11];
    const float* b_h    = (const float*)d_in[12];
    float* out = (float*)d_out;

    for (int step=0; step<5; ++step){
        const int use_x = (step==0), fin = (step==4);
        proj_kernel<<<dim3(16,8,4),256>>>(x, W_ein,b_ein,W_eout,b_eout, use_x);
        agg_kernel <<<dim3(16,2,4),256>>>(A_in, A_out);
        gru_kernel <<<dim3(16,1,4),256>>>(x, W_r,b_r,W_z,b_z,W_h,b_h, out, use_x, fin);
    }
}